// round 15
// baseline (speedup 1.0000x reference)
#include <cuda_runtime.h>
#include <cuda_fp16.h>
#include <cstdint>

#define OUT_F 11008
#define IN_F  4096
#define M_ROWS 8192

static constexpr size_t W_ELEMS = (size_t)OUT_F * IN_F;
static constexpr size_t X_ELEMS = (size_t)M_ROWS * IN_F;

// Single merged scratch buffer: W fp16 at [0, W_ELEMS), X fp16 at [W_ELEMS, +X_ELEMS)
__device__ __half g_buf[W_ELEMS + X_ELEMS];

__constant__ float c_code[16] = {
    -1.0f, -0.6961928009986877f, -0.5250730514526367f, -0.39491748809814453f,
    -0.28444138169288635f, -0.18477343022823334f, -0.09105003625154495f, 0.0f,
    0.07958029955625534f, 0.16093020141124725f, 0.24611230194568634f,
    0.33791524171829224f, 0.44070982933044434f, 0.5626170039176941f,
    0.7229568362236023f, 1.0f };

// ---------------------------------------------------------------------------
// Fused prep (R8 form — best measured): blocks [0, WB) dequant W
// (16 w/thread, smem NF4 table), blocks [WB, WB+XB) convert x (8 f/thread).
// ---------------------------------------------------------------------------
static constexpr int WB = (int)(W_ELEMS / 16 / 256);   // 11008
static constexpr int XB = (int)(X_ELEMS / 8 / 256);    // 16384

__global__ void __launch_bounds__(256)
prep_kernel(const float* __restrict__ x, const int* __restrict__ idx,
            const float* __restrict__ absmax)
{
    __shared__ float s_code[16];
    if (threadIdx.x < 16) s_code[threadIdx.x] = c_code[threadIdx.x];
    __syncthreads();

    const int bid = blockIdx.x;
    if (bid < WB) {
        size_t t = (size_t)bid * 256 + threadIdx.x;   // 16 weights / thread
        float am = __ldg(&absmax[t >> 2]);
        int4 q0 = __ldcs(&reinterpret_cast<const int4*>(idx)[t * 4 + 0]);
        int4 q1 = __ldcs(&reinterpret_cast<const int4*>(idx)[t * 4 + 1]);
        int4 q2 = __ldcs(&reinterpret_cast<const int4*>(idx)[t * 4 + 2]);
        int4 q3 = __ldcs(&reinterpret_cast<const int4*>(idx)[t * 4 + 3]);
        __half2 h[8];
        h[0] = __floats2half2_rn(s_code[q0.x] * am, s_code[q0.y] * am);
        h[1] = __floats2half2_rn(s_code[q0.z] * am, s_code[q0.w] * am);
        h[2] = __floats2half2_rn(s_code[q1.x] * am, s_code[q1.y] * am);
        h[3] = __floats2half2_rn(s_code[q1.z] * am, s_code[q1.w] * am);
        h[4] = __floats2half2_rn(s_code[q2.x] * am, s_code[q2.y] * am);
        h[5] = __floats2half2_rn(s_code[q2.z] * am, s_code[q2.w] * am);
        h[6] = __floats2half2_rn(s_code[q3.x] * am, s_code[q3.y] * am);
        h[7] = __floats2half2_rn(s_code[q3.z] * am, s_code[q3.w] * am);
        uint4* dst = reinterpret_cast<uint4*>(&g_buf[t * 16]);
        __stcs(dst + 0, reinterpret_cast<uint4*>(h)[0]);
        __stcs(dst + 1, reinterpret_cast<uint4*>(h)[1]);
    } else {
        size_t t = (size_t)(bid - WB) * 256 + threadIdx.x;   // 8 floats / thread
        float4 v0 = __ldcs(&reinterpret_cast<const float4*>(x)[t * 2 + 0]);
        float4 v1 = __ldcs(&reinterpret_cast<const float4*>(x)[t * 2 + 1]);
        __half2 h[4];
        h[0] = __floats2half2_rn(v0.x, v0.y);
        h[1] = __floats2half2_rn(v0.z, v0.w);
        h[2] = __floats2half2_rn(v1.x, v1.y);
        h[3] = __floats2half2_rn(v1.z, v1.w);
        __stcs(reinterpret_cast<uint4*>(&g_buf[W_ELEMS + t * 8]), *reinterpret_cast<uint4*>(h));
    }
}

// ---------------------------------------------------------------------------
// GEMM: R13 config + finest-grain MMA/LDSM interleave (LDSM split into
// 2-instruction slivers between every mi-group of MMAs).
//   C[M,N] = A[M,K] * B[N,K]^T   CTA 128x128x64, 256 thr, 8 warps (2M x 4N),
//   warp tile 64x32, 3-stage cp.async (96 KB), occ 2, frag double-buffered.
// ---------------------------------------------------------------------------
static constexpr int BM = 128, BN = 128, BK = 64, STAGES = 3;
static constexpr int A_BYTES = BM * BK * 2;                 // 16384
static constexpr int STAGE_BYTES = 2 * A_BYTES;             // 32768
static constexpr int SMEM_DYN = STAGES * STAGE_BYTES;       // 98304
static constexpr int K_ITERS = IN_F / BK;                   // 64
static constexpr int TILES_M = M_ROWS / BM;                 // 64
static constexpr int TILES_N = OUT_F / BN;                  // 86
static constexpr int GROUP_M = 8;

__device__ __forceinline__ uint32_t smem_u32(const void* p) {
    uint32_t a;
    asm("{ .reg .u64 t; cvta.to.shared.u64 t, %1; cvt.u32.u64 %0, t; }" : "=r"(a) : "l"(p));
    return a;
}
__device__ __forceinline__ void cp16(uint32_t s, const void* g) {
    asm volatile("cp.async.cg.shared.global [%0], [%1], 16;" :: "r"(s), "l"(g) : "memory");
}
__device__ __forceinline__ void cp_commit() {
    asm volatile("cp.async.commit_group;" ::: "memory");
}
template <int N>
__device__ __forceinline__ void cp_wait() {
    asm volatile("cp.async.wait_group %0;" :: "n"(N) : "memory");
}
__device__ __forceinline__ void ldsm4(uint32_t* r, uint32_t a) {
    asm volatile("ldmatrix.sync.aligned.m8n8.x4.shared.b16 {%0,%1,%2,%3}, [%4];"
        : "=r"(r[0]), "=r"(r[1]), "=r"(r[2]), "=r"(r[3]) : "r"(a));
}
__device__ __forceinline__ void mma16816(float* c, const uint32_t* a, uint32_t b0, uint32_t b1) {
    asm volatile(
        "mma.sync.aligned.m16n8k16.row.col.f32.f16.f16.f32 "
        "{%0,%1,%2,%3}, {%4,%5,%6,%7}, {%8,%9}, {%0,%1,%2,%3};"
        : "+f"(c[0]), "+f"(c[1]), "+f"(c[2]), "+f"(c[3])
        : "r"(a[0]), "r"(a[1]), "r"(a[2]), "r"(a[3]), "r"(b0), "r"(b1));
}

__global__ void __launch_bounds__(256, 2)
gemm_kernel(const float* __restrict__ bias, float* __restrict__ out)
{
    extern __shared__ char smem_raw[];
    const uint32_t smem = smem_u32(smem_raw);
    const int tid = threadIdx.x, wid = tid >> 5, lane = tid & 31;

    // ---- GROUP_M rasterization ----
    const int bid = blockIdx.x;
    const int per_group = GROUP_M * TILES_N;
    const int grp = bid / per_group;
    const int rem = bid - grp * per_group;
    const int m0 = (grp * GROUP_M + (rem % GROUP_M)) * BM;
    const int n0 = (rem / GROUP_M) * BN;

    // ---- loader: thread t -> row t/8 (+32 per pass), 16B chunk t%8 ----
    const int lrow = tid >> 3;                                 // 0..31
    const int lchk = tid & 7;                                  // 0..7
    const uint32_t ld_soff = (uint32_t)lrow * 128 + (uint32_t)((lchk ^ (lrow & 7)) << 4);
    const __half* gB = &g_buf[(size_t)(n0 + lrow) * IN_F + lchk * 8];
    const __half* gA = &g_buf[W_ELEMS + (size_t)(m0 + lrow) * IN_F + lchk * 8];

    // ---- compute mapping: 2 M-warps x 4 N-warps, warp tile 64x32 ----
    const int wm = (wid & 1) * 64;
    const int wn = (wid >> 1) * 32;
    const int lr = lane & 15, hi = lane >> 4, lo = lane & 7;

    uint32_t a_base[4], b_base[2];
    #pragma unroll
    for (int mi = 0; mi < 4; mi++) a_base[mi] = (uint32_t)(wm + mi * 16 + lr) * 128;
    #pragma unroll
    for (int ni = 0; ni < 2; ni++) b_base[ni] = (uint32_t)A_BYTES + (uint32_t)(wn + ni * 16 + lr) * 128;

    float acc[4][4][4];
    #pragma unroll
    for (int mi = 0; mi < 4; mi++)
        #pragma unroll
        for (int nj = 0; nj < 4; nj++)
            #pragma unroll
            for (int r = 0; r < 4; r++) acc[mi][nj][r] = 0.0f;

    // ---- prologue: fill stages 0,1 ----
    #pragma unroll
    for (int s = 0; s < STAGES - 1; s++) {
        uint32_t base = smem + s * STAGE_BYTES;
        #pragma unroll
        for (int p = 0; p < 4; p++) {
            cp16(base + ld_soff + p * 32 * 128,           gA + (size_t)s * BK + (size_t)p * 32 * IN_F);
            cp16(base + A_BYTES + ld_soff + p * 32 * 128, gB + (size_t)s * BK + (size_t)p * 32 * IN_F);
        }
        cp_commit();
    }
    gA += (STAGES - 1) * BK;
    gB += (STAGES - 1) * BK;

    uint32_t sc = smem;
    uint32_t sfill = smem + (STAGES - 1) * STAGE_BYTES;
    const uint32_t ring_end = smem + STAGES * STAGE_BYTES;

    uint32_t af[2][4][4], bf[2][2][4];   // double-buffered fragments

    // ---- mainloop ----
    for (int kt = 0; kt < K_ITERS; kt++) {
        cp_wait<STAGES - 2>();
        __syncthreads();
        const bool fill = (kt + STAGES - 1 < K_ITERS);

        // frag prefetch for ks = 0
        {
            const uint32_t swz0 = (uint32_t)((hi ^ lo) << 4);
            #pragma unroll
            for (int mi = 0; mi < 4; mi++) ldsm4(af[0][mi], sc + a_base[mi] + swz0);
            #pragma unroll
            for (int ni = 0; ni < 2; ni++) ldsm4(bf[0][ni], sc + b_base[ni] + swz0);
        }

        #pragma unroll
        for (int ks = 0; ks < BK / 16; ks++) {
            const int cur = ks & 1, nx = cur ^ 1;
            const bool pre = (ks < BK / 16 - 1);
            const uint32_t swz = (uint32_t)((((ks + 1) * 2 + hi) ^ lo) << 4);

            // mi0 MMAs
            #pragma unroll
            for (int ni = 0; ni < 2; ni++) {
                mma16816(acc[0][2 * ni + 0], af[cur][0], bf[cur][ni][0], bf[cur][ni][2]);
                mma16816(acc[0][2 * ni + 1], af[cur][0], bf[cur][ni][1], bf[cur][ni][3]);
            }
            // LDSM sliver: A frags 0,1
            if (pre) { ldsm4(af[nx][0], sc + a_base[0] + swz); ldsm4(af[nx][1], sc + a_base[1] + swz); }

            // mi1 MMAs
            #pragma unroll
            for (int ni = 0; ni < 2; ni++) {
                mma16816(acc[1][2 * ni + 0], af[cur][1], bf[cur][ni][0], bf[cur][ni][2]);
                mma16816(acc[1][2 * ni + 1], af[cur][1], bf[cur][ni][1], bf[cur][ni][3]);
            }
            // LDSM sliver: A frags 2,3
            if (pre) { ldsm4(af[nx][2], sc + a_base[2] + swz); ldsm4(af[nx][3], sc + a_base[3] + swz); }

            // mi2 MMAs
            #pragma unroll
            for (int ni = 0; ni < 2; ni++) {
                mma16816(acc[2][2 * ni + 0], af[cur][2], bf[cur][ni][0], bf[cur][ni][2]);
                mma16816(acc[2][2 * ni + 1], af[cur][2], bf[cur][ni][1], bf[cur][ni][3]);
            }
            // LDSM sliver: B frags 0,1 + fill cp16 pair
            if (pre) { ldsm4(bf[nx][0], sc + b_base[0] + swz); ldsm4(bf[nx][1], sc + b_base[1] + swz); }
            if (fill) {
                cp16(sfill + ld_soff + ks * 32 * 128,           gA + (size_t)ks * 32 * IN_F);
                cp16(sfill + A_BYTES + ld_soff + ks * 32 * 128, gB + (size_t)ks * 32 * IN_F);
            }

            // mi3 MMAs
            #pragma unroll
            for (int ni = 0; ni < 2; ni++) {
                mma16816(acc[3][2 * ni + 0], af[cur][3], bf[cur][ni][0], bf[cur][ni][2]);
                mma16816(acc[3][2 * ni + 1], af[cur][3], bf[cur][ni][1], bf[cur][ni][3]);
            }
        }
        cp_commit();
        sc += STAGE_BYTES;    if (sc == ring_end) sc = smem;
        sfill += STAGE_BYTES; if (sfill == ring_end) sfill = smem;
        gA += BK;
        gB += BK;
    }

    // ---- epilogue: streaming stores (keep output out of L2) ----
    const int er = m0 + wm + (lane >> 2);
    const int ec = n0 + wn + ((lane & 3) << 1);
    #pragma unroll
    for (int mi = 0; mi < 4; mi++) {
        #pragma unroll
        for (int nj = 0; nj < 4; nj++) {
            const int row = er + mi * 16;
            const int col = ec + nj * 8;
            float2 bv = *reinterpret_cast<const float2*>(&bias[col]);
            float2 v0 = { acc[mi][nj][0] + bv.x, acc[mi][nj][1] + bv.y };
            float2 v1 = { acc[mi][nj][2] + bv.x, acc[mi][nj][3] + bv.y };
            __stcs(reinterpret_cast<float2*>(&out[(size_t)row * OUT_F + col]), v0);
            __stcs(reinterpret_cast<float2*>(&out[(size_t)(row + 8) * OUT_F + col]), v1);
        }
    }
}

// ---------------------------------------------------------------------------
// Host
// ---------------------------------------------------------------------------
extern "C" void kernel_launch(void* const* d_in, const int* in_sizes, int n_in,
                              void* d_out, int out_size)
{
    const float* x      = (const float*)d_in[0];
    const int*   w_idx  = (const int*)d_in[1];
    const float* absmax = (const float*)d_in[2];
    const float* bias   = (const float*)d_in[3];
    float*       out    = (float*)d_out;

    prep_kernel<<<WB + XB, 256>>>(x, w_idx, absmax);

    cudaFuncSetAttribute(gemm_kernel, cudaFuncAttributeMaxDynamicSharedMemorySize, SMEM_DYN);
    gemm_kernel<<<TILES_M * TILES_N, 256, SMEM_DYN>>>(bias, out);
    (void)in_sizes; (void)n_in; (void)out_size;
}

// round 16
// speedup vs baseline: 1.0187x; 1.0187x over previous
#include <cuda_runtime.h>
#include <cuda_fp16.h>
#include <cstdint>

#define OUT_F 11008
#define IN_F  4096
#define M_ROWS 8192

static constexpr size_t W_ELEMS = (size_t)OUT_F * IN_F;
static constexpr size_t X_ELEMS = (size_t)M_ROWS * IN_F;

// Single merged scratch buffer: W fp16 at [0, W_ELEMS), X fp16 at [W_ELEMS, +X_ELEMS)
__device__ __half g_buf[W_ELEMS + X_ELEMS];

__constant__ float c_code[16] = {
    -1.0f, -0.6961928009986877f, -0.5250730514526367f, -0.39491748809814453f,
    -0.28444138169288635f, -0.18477343022823334f, -0.09105003625154495f, 0.0f,
    0.07958029955625534f, 0.16093020141124725f, 0.24611230194568634f,
    0.33791524171829224f, 0.44070982933044434f, 0.5626170039176941f,
    0.7229568362236023f, 1.0f };

// ---------------------------------------------------------------------------
// Fused prep (R8 form — best measured): blocks [0, WB) dequant W
// (16 w/thread, smem NF4 table), blocks [WB, WB+XB) convert x (8 f/thread).
// ---------------------------------------------------------------------------
static constexpr int WB = (int)(W_ELEMS / 16 / 256);   // 11008
static constexpr int XB = (int)(X_ELEMS / 8 / 256);    // 16384

__global__ void __launch_bounds__(256)
prep_kernel(const float* __restrict__ x, const int* __restrict__ idx,
            const float* __restrict__ absmax)
{
    __shared__ float s_code[16];
    if (threadIdx.x < 16) s_code[threadIdx.x] = c_code[threadIdx.x];
    __syncthreads();

    const int bid = blockIdx.x;
    if (bid < WB) {
        size_t t = (size_t)bid * 256 + threadIdx.x;   // 16 weights / thread
        float am = __ldg(&absmax[t >> 2]);
        int4 q0 = __ldcs(&reinterpret_cast<const int4*>(idx)[t * 4 + 0]);
        int4 q1 = __ldcs(&reinterpret_cast<const int4*>(idx)[t * 4 + 1]);
        int4 q2 = __ldcs(&reinterpret_cast<const int4*>(idx)[t * 4 + 2]);
        int4 q3 = __ldcs(&reinterpret_cast<const int4*>(idx)[t * 4 + 3]);
        __half2 h[8];
        h[0] = __floats2half2_rn(s_code[q0.x] * am, s_code[q0.y] * am);
        h[1] = __floats2half2_rn(s_code[q0.z] * am, s_code[q0.w] * am);
        h[2] = __floats2half2_rn(s_code[q1.x] * am, s_code[q1.y] * am);
        h[3] = __floats2half2_rn(s_code[q1.z] * am, s_code[q1.w] * am);
        h[4] = __floats2half2_rn(s_code[q2.x] * am, s_code[q2.y] * am);
        h[5] = __floats2half2_rn(s_code[q2.z] * am, s_code[q2.w] * am);
        h[6] = __floats2half2_rn(s_code[q3.x] * am, s_code[q3.y] * am);
        h[7] = __floats2half2_rn(s_code[q3.z] * am, s_code[q3.w] * am);
        uint4* dst = reinterpret_cast<uint4*>(&g_buf[t * 16]);
        __stcs(dst + 0, reinterpret_cast<uint4*>(h)[0]);
        __stcs(dst + 1, reinterpret_cast<uint4*>(h)[1]);
    } else {
        size_t t = (size_t)(bid - WB) * 256 + threadIdx.x;   // 8 floats / thread
        float4 v0 = __ldcs(&reinterpret_cast<const float4*>(x)[t * 2 + 0]);
        float4 v1 = __ldcs(&reinterpret_cast<const float4*>(x)[t * 2 + 1]);
        __half2 h[4];
        h[0] = __floats2half2_rn(v0.x, v0.y);
        h[1] = __floats2half2_rn(v0.z, v0.w);
        h[2] = __floats2half2_rn(v1.x, v1.y);
        h[3] = __floats2half2_rn(v1.z, v1.w);
        __stcs(reinterpret_cast<uint4*>(&g_buf[W_ELEMS + t * 8]), *reinterpret_cast<uint4*>(h));
    }
}

// ---------------------------------------------------------------------------
// GEMM: R13 — measured optimum (1977.7us total, tensor 69.6%).
//   C[M,N] = A[M,K] * B[N,K]^T   CTA 128x128x64, 256 thr, 8 warps (2M x 4N),
//   warp tile 64x32, 3-stage cp.async (96 KB), occ 2, frag double-buffered,
//   coarse MMA/LDSM sandwich (MMA mi0,1 -> LDSM batch + fill -> MMA mi2,3),
//   streaming epilogue stores.
// ---------------------------------------------------------------------------
static constexpr int BM = 128, BN = 128, BK = 64, STAGES = 3;
static constexpr int A_BYTES = BM * BK * 2;                 // 16384
static constexpr int STAGE_BYTES = 2 * A_BYTES;             // 32768
static constexpr int SMEM_DYN = STAGES * STAGE_BYTES;       // 98304
static constexpr int K_ITERS = IN_F / BK;                   // 64
static constexpr int TILES_M = M_ROWS / BM;                 // 64
static constexpr int TILES_N = OUT_F / BN;                  // 86
static constexpr int GROUP_M = 8;

__device__ __forceinline__ uint32_t smem_u32(const void* p) {
    uint32_t a;
    asm("{ .reg .u64 t; cvta.to.shared.u64 t, %1; cvt.u32.u64 %0, t; }" : "=r"(a) : "l"(p));
    return a;
}
__device__ __forceinline__ void cp16(uint32_t s, const void* g) {
    asm volatile("cp.async.cg.shared.global [%0], [%1], 16;" :: "r"(s), "l"(g) : "memory");
}
__device__ __forceinline__ void cp_commit() {
    asm volatile("cp.async.commit_group;" ::: "memory");
}
template <int N>
__device__ __forceinline__ void cp_wait() {
    asm volatile("cp.async.wait_group %0;" :: "n"(N) : "memory");
}
__device__ __forceinline__ void ldsm4(uint32_t* r, uint32_t a) {
    asm volatile("ldmatrix.sync.aligned.m8n8.x4.shared.b16 {%0,%1,%2,%3}, [%4];"
        : "=r"(r[0]), "=r"(r[1]), "=r"(r[2]), "=r"(r[3]) : "r"(a));
}
__device__ __forceinline__ void mma16816(float* c, const uint32_t* a, uint32_t b0, uint32_t b1) {
    asm volatile(
        "mma.sync.aligned.m16n8k16.row.col.f32.f16.f16.f32 "
        "{%0,%1,%2,%3}, {%4,%5,%6,%7}, {%8,%9}, {%0,%1,%2,%3};"
        : "+f"(c[0]), "+f"(c[1]), "+f"(c[2]), "+f"(c[3])
        : "r"(a[0]), "r"(a[1]), "r"(a[2]), "r"(a[3]), "r"(b0), "r"(b1));
}

__global__ void __launch_bounds__(256, 2)
gemm_kernel(const float* __restrict__ bias, float* __restrict__ out)
{
    extern __shared__ char smem_raw[];
    const uint32_t smem = smem_u32(smem_raw);
    const int tid = threadIdx.x, wid = tid >> 5, lane = tid & 31;

    // ---- GROUP_M rasterization ----
    const int bid = blockIdx.x;
    const int per_group = GROUP_M * TILES_N;
    const int grp = bid / per_group;
    const int rem = bid - grp * per_group;
    const int m0 = (grp * GROUP_M + (rem % GROUP_M)) * BM;
    const int n0 = (rem / GROUP_M) * BN;

    // ---- loader: thread t -> row t/8 (+32 per pass), 16B chunk t%8 ----
    const int lrow = tid >> 3;                                 // 0..31
    const int lchk = tid & 7;                                  // 0..7
    const uint32_t ld_soff = (uint32_t)lrow * 128 + (uint32_t)((lchk ^ (lrow & 7)) << 4);
    const __half* gB = &g_buf[(size_t)(n0 + lrow) * IN_F + lchk * 8];
    const __half* gA = &g_buf[W_ELEMS + (size_t)(m0 + lrow) * IN_F + lchk * 8];

    // ---- compute mapping: 2 M-warps x 4 N-warps, warp tile 64x32 ----
    const int wm = (wid & 1) * 64;
    const int wn = (wid >> 1) * 32;
    const int lr = lane & 15, hi = lane >> 4, lo = lane & 7;

    uint32_t a_base[4], b_base[2];
    #pragma unroll
    for (int mi = 0; mi < 4; mi++) a_base[mi] = (uint32_t)(wm + mi * 16 + lr) * 128;
    #pragma unroll
    for (int ni = 0; ni < 2; ni++) b_base[ni] = (uint32_t)A_BYTES + (uint32_t)(wn + ni * 16 + lr) * 128;

    float acc[4][4][4];
    #pragma unroll
    for (int mi = 0; mi < 4; mi++)
        #pragma unroll
        for (int nj = 0; nj < 4; nj++)
            #pragma unroll
            for (int r = 0; r < 4; r++) acc[mi][nj][r] = 0.0f;

    // ---- prologue: fill stages 0,1 ----
    #pragma unroll
    for (int s = 0; s < STAGES - 1; s++) {
        uint32_t base = smem + s * STAGE_BYTES;
        #pragma unroll
        for (int p = 0; p < 4; p++) {
            cp16(base + ld_soff + p * 32 * 128,           gA + (size_t)s * BK + (size_t)p * 32 * IN_F);
            cp16(base + A_BYTES + ld_soff + p * 32 * 128, gB + (size_t)s * BK + (size_t)p * 32 * IN_F);
        }
        cp_commit();
    }
    gA += (STAGES - 1) * BK;
    gB += (STAGES - 1) * BK;

    uint32_t sc = smem;
    uint32_t sfill = smem + (STAGES - 1) * STAGE_BYTES;
    const uint32_t ring_end = smem + STAGES * STAGE_BYTES;

    uint32_t af[2][4][4], bf[2][2][4];   // double-buffered fragments

    // ---- mainloop ----
    for (int kt = 0; kt < K_ITERS; kt++) {
        cp_wait<STAGES - 2>();
        __syncthreads();
        const bool fill = (kt + STAGES - 1 < K_ITERS);

        // frag prefetch for ks = 0
        {
            const uint32_t swz0 = (uint32_t)((hi ^ lo) << 4);
            #pragma unroll
            for (int mi = 0; mi < 4; mi++) ldsm4(af[0][mi], sc + a_base[mi] + swz0);
            #pragma unroll
            for (int ni = 0; ni < 2; ni++) ldsm4(bf[0][ni], sc + b_base[ni] + swz0);
        }

        #pragma unroll
        for (int ks = 0; ks < BK / 16; ks++) {
            const int cur = ks & 1, nx = cur ^ 1;

            // first half of MMAs (mi 0,1) — HMMA work available before LDSM drain
            #pragma unroll
            for (int mi = 0; mi < 2; mi++) {
                #pragma unroll
                for (int ni = 0; ni < 2; ni++) {
                    mma16816(acc[mi][2 * ni + 0], af[cur][mi], bf[cur][ni][0], bf[cur][ni][2]);
                    mma16816(acc[mi][2 * ni + 1], af[cur][mi], bf[cur][ni][1], bf[cur][ni][3]);
                }
            }

            // LDSM prefetch for next ks, sandwiched between MMA halves
            if (ks < BK / 16 - 1) {
                const uint32_t swz = (uint32_t)((((ks + 1) * 2 + hi) ^ lo) << 4);
                #pragma unroll
                for (int mi = 0; mi < 4; mi++) ldsm4(af[nx][mi], sc + a_base[mi] + swz);
                #pragma unroll
                for (int ni = 0; ni < 2; ni++) ldsm4(bf[nx][ni], sc + b_base[ni] + swz);
            }
            // spread fill: 2 cp16 per ks step
            if (fill) {
                cp16(sfill + ld_soff + ks * 32 * 128,           gA + (size_t)ks * 32 * IN_F);
                cp16(sfill + A_BYTES + ld_soff + ks * 32 * 128, gB + (size_t)ks * 32 * IN_F);
            }

            // second half of MMAs (mi 2,3) — covers LDSM latency
            #pragma unroll
            for (int mi = 2; mi < 4; mi++) {
                #pragma unroll
                for (int ni = 0; ni < 2; ni++) {
                    mma16816(acc[mi][2 * ni + 0], af[cur][mi], bf[cur][ni][0], bf[cur][ni][2]);
                    mma16816(acc[mi][2 * ni + 1], af[cur][mi], bf[cur][ni][1], bf[cur][ni][3]);
                }
            }
        }
        cp_commit();
        sc += STAGE_BYTES;    if (sc == ring_end) sc = smem;
        sfill += STAGE_BYTES; if (sfill == ring_end) sfill = smem;
        gA += BK;
        gB += BK;
    }

    // ---- epilogue: streaming stores (keep output out of L2) ----
    const int er = m0 + wm + (lane >> 2);
    const int ec = n0 + wn + ((lane & 3) << 1);
    #pragma unroll
    for (int mi = 0; mi < 4; mi++) {
        #pragma unroll
        for (int nj = 0; nj < 4; nj++) {
            const int row = er + mi * 16;
            const int col = ec + nj * 8;
            float2 bv = *reinterpret_cast<const float2*>(&bias[col]);
            float2 v0 = { acc[mi][nj][0] + bv.x, acc[mi][nj][1] + bv.y };
            float2 v1 = { acc[mi][nj][2] + bv.x, acc[mi][nj][3] + bv.y };
            __stcs(reinterpret_cast<float2*>(&out[(size_t)row * OUT_F + col]), v0);
            __stcs(reinterpret_cast<float2*>(&out[(size_t)(row + 8) * OUT_F + col]), v1);
        }
    }
}

// ---------------------------------------------------------------------------
// Host
// ---------------------------------------------------------------------------
extern "C" void kernel_launch(void* const* d_in, const int* in_sizes, int n_in,
                              void* d_out, int out_size)
{
    const float* x      = (const float*)d_in[0];
    const int*   w_idx  = (const int*)d_in[1];
    const float* absmax = (const float*)d_in[2];
    const float* bias   = (const float*)d_in[3];
    float*       out    = (float*)d_out;

    prep_kernel<<<WB + XB, 256>>>(x, w_idx, absmax);

    cudaFuncSetAttribute(gemm_kernel, cudaFuncAttributeMaxDynamicSharedMemorySize, SMEM_DYN);
    gemm_kernel<<<TILES_M * TILES_N, 256, SMEM_DYN>>>(bias, out);
    (void)in_sizes; (void)n_in; (void)out_size;
}

// round 17
// speedup vs baseline: 1.0216x; 1.0028x over previous
#include <cuda_runtime.h>
#include <cuda_fp16.h>
#include <cstdint>

#define OUT_F 11008
#define IN_F  4096
#define M_ROWS 8192

static constexpr size_t W_ELEMS = (size_t)OUT_F * IN_F;
static constexpr size_t X_ELEMS = (size_t)M_ROWS * IN_F;

// Single merged scratch buffer: W fp16 at [0, W_ELEMS), X fp16 at [W_ELEMS, +X_ELEMS)
__device__ __half g_buf[W_ELEMS + X_ELEMS];

__constant__ float c_code[16] = {
    -1.0f, -0.6961928009986877f, -0.5250730514526367f, -0.39491748809814453f,
    -0.28444138169288635f, -0.18477343022823334f, -0.09105003625154495f, 0.0f,
    0.07958029955625534f, 0.16093020141124725f, 0.24611230194568634f,
    0.33791524171829224f, 0.44070982933044434f, 0.5626170039176941f,
    0.7229568362236023f, 1.0f };

// ---------------------------------------------------------------------------
// Fused prep (R8 form — best measured): blocks [0, WB) dequant W
// (16 w/thread, smem NF4 table), blocks [WB, WB+XB) convert x (8 f/thread).
// ---------------------------------------------------------------------------
static constexpr int WB = (int)(W_ELEMS / 16 / 256);   // 11008
static constexpr int XB = (int)(X_ELEMS / 8 / 256);    // 16384

__global__ void __launch_bounds__(256)
prep_kernel(const float* __restrict__ x, const int* __restrict__ idx,
            const float* __restrict__ absmax)
{
    __shared__ float s_code[16];
    if (threadIdx.x < 16) s_code[threadIdx.x] = c_code[threadIdx.x];
    __syncthreads();

    const int bid = blockIdx.x;
    if (bid < WB) {
        size_t t = (size_t)bid * 256 + threadIdx.x;   // 16 weights / thread
        float am = __ldg(&absmax[t >> 2]);
        int4 q0 = __ldcs(&reinterpret_cast<const int4*>(idx)[t * 4 + 0]);
        int4 q1 = __ldcs(&reinterpret_cast<const int4*>(idx)[t * 4 + 1]);
        int4 q2 = __ldcs(&reinterpret_cast<const int4*>(idx)[t * 4 + 2]);
        int4 q3 = __ldcs(&reinterpret_cast<const int4*>(idx)[t * 4 + 3]);
        __half2 h[8];
        h[0] = __floats2half2_rn(s_code[q0.x] * am, s_code[q0.y] * am);
        h[1] = __floats2half2_rn(s_code[q0.z] * am, s_code[q0.w] * am);
        h[2] = __floats2half2_rn(s_code[q1.x] * am, s_code[q1.y] * am);
        h[3] = __floats2half2_rn(s_code[q1.z] * am, s_code[q1.w] * am);
        h[4] = __floats2half2_rn(s_code[q2.x] * am, s_code[q2.y] * am);
        h[5] = __floats2half2_rn(s_code[q2.z] * am, s_code[q2.w] * am);
        h[6] = __floats2half2_rn(s_code[q3.x] * am, s_code[q3.y] * am);
        h[7] = __floats2half2_rn(s_code[q3.z] * am, s_code[q3.w] * am);
        uint4* dst = reinterpret_cast<uint4*>(&g_buf[t * 16]);
        __stcs(dst + 0, reinterpret_cast<uint4*>(h)[0]);
        __stcs(dst + 1, reinterpret_cast<uint4*>(h)[1]);
    } else {
        size_t t = (size_t)(bid - WB) * 256 + threadIdx.x;   // 8 floats / thread
        float4 v0 = __ldcs(&reinterpret_cast<const float4*>(x)[t * 2 + 0]);
        float4 v1 = __ldcs(&reinterpret_cast<const float4*>(x)[t * 2 + 1]);
        __half2 h[4];
        h[0] = __floats2half2_rn(v0.x, v0.y);
        h[1] = __floats2half2_rn(v0.z, v0.w);
        h[2] = __floats2half2_rn(v1.x, v1.y);
        h[3] = __floats2half2_rn(v1.z, v1.w);
        __stcs(reinterpret_cast<uint4*>(&g_buf[W_ELEMS + t * 8]), *reinterpret_cast<uint4*>(h));
    }
}

// ---------------------------------------------------------------------------
// GEMM: R13 measured optimum + fill-first micro-tweak (cp16 pair issued at
// the top of each ks step so the LSU gets maximal lead time).
//   C[M,N] = A[M,K] * B[N,K]^T   CTA 128x128x64, 256 thr, 8 warps (2M x 4N),
//   warp tile 64x32, 3-stage cp.async (96 KB), occ 2, frag double-buffered,
//   coarse MMA/LDSM sandwich, streaming epilogue stores.
// ---------------------------------------------------------------------------
static constexpr int BM = 128, BN = 128, BK = 64, STAGES = 3;
static constexpr int A_BYTES = BM * BK * 2;                 // 16384
static constexpr int STAGE_BYTES = 2 * A_BYTES;             // 32768
static constexpr int SMEM_DYN = STAGES * STAGE_BYTES;       // 98304
static constexpr int K_ITERS = IN_F / BK;                   // 64
static constexpr int TILES_M = M_ROWS / BM;                 // 64
static constexpr int TILES_N = OUT_F / BN;                  // 86
static constexpr int GROUP_M = 8;

__device__ __forceinline__ uint32_t smem_u32(const void* p) {
    uint32_t a;
    asm("{ .reg .u64 t; cvta.to.shared.u64 t, %1; cvt.u32.u64 %0, t; }" : "=r"(a) : "l"(p));
    return a;
}
__device__ __forceinline__ void cp16(uint32_t s, const void* g) {
    asm volatile("cp.async.cg.shared.global [%0], [%1], 16;" :: "r"(s), "l"(g) : "memory");
}
__device__ __forceinline__ void cp_commit() {
    asm volatile("cp.async.commit_group;" ::: "memory");
}
template <int N>
__device__ __forceinline__ void cp_wait() {
    asm volatile("cp.async.wait_group %0;" :: "n"(N) : "memory");
}
__device__ __forceinline__ void ldsm4(uint32_t* r, uint32_t a) {
    asm volatile("ldmatrix.sync.aligned.m8n8.x4.shared.b16 {%0,%1,%2,%3}, [%4];"
        : "=r"(r[0]), "=r"(r[1]), "=r"(r[2]), "=r"(r[3]) : "r"(a));
}
__device__ __forceinline__ void mma16816(float* c, const uint32_t* a, uint32_t b0, uint32_t b1) {
    asm volatile(
        "mma.sync.aligned.m16n8k16.row.col.f32.f16.f16.f32 "
        "{%0,%1,%2,%3}, {%4,%5,%6,%7}, {%8,%9}, {%0,%1,%2,%3};"
        : "+f"(c[0]), "+f"(c[1]), "+f"(c[2]), "+f"(c[3])
        : "r"(a[0]), "r"(a[1]), "r"(a[2]), "r"(a[3]), "r"(b0), "r"(b1));
}

__global__ void __launch_bounds__(256, 2)
gemm_kernel(const float* __restrict__ bias, float* __restrict__ out)
{
    extern __shared__ char smem_raw[];
    const uint32_t smem = smem_u32(smem_raw);
    const int tid = threadIdx.x, wid = tid >> 5, lane = tid & 31;

    // ---- GROUP_M rasterization ----
    const int bid = blockIdx.x;
    const int per_group = GROUP_M * TILES_N;
    const int grp = bid / per_group;
    const int rem = bid - grp * per_group;
    const int m0 = (grp * GROUP_M + (rem % GROUP_M)) * BM;
    const int n0 = (rem / GROUP_M) * BN;

    // ---- loader: thread t -> row t/8 (+32 per pass), 16B chunk t%8 ----
    const int lrow = tid >> 3;                                 // 0..31
    const int lchk = tid & 7;                                  // 0..7
    const uint32_t ld_soff = (uint32_t)lrow * 128 + (uint32_t)((lchk ^ (lrow & 7)) << 4);
    const __half* gB = &g_buf[(size_t)(n0 + lrow) * IN_F + lchk * 8];
    const __half* gA = &g_buf[W_ELEMS + (size_t)(m0 + lrow) * IN_F + lchk * 8];

    // ---- compute mapping: 2 M-warps x 4 N-warps, warp tile 64x32 ----
    const int wm = (wid & 1) * 64;
    const int wn = (wid >> 1) * 32;
    const int lr = lane & 15, hi = lane >> 4, lo = lane & 7;

    uint32_t a_base[4], b_base[2];
    #pragma unroll
    for (int mi = 0; mi < 4; mi++) a_base[mi] = (uint32_t)(wm + mi * 16 + lr) * 128;
    #pragma unroll
    for (int ni = 0; ni < 2; ni++) b_base[ni] = (uint32_t)A_BYTES + (uint32_t)(wn + ni * 16 + lr) * 128;

    float acc[4][4][4];
    #pragma unroll
    for (int mi = 0; mi < 4; mi++)
        #pragma unroll
        for (int nj = 0; nj < 4; nj++)
            #pragma unroll
            for (int r = 0; r < 4; r++) acc[mi][nj][r] = 0.0f;

    // ---- prologue: fill stages 0,1 ----
    #pragma unroll
    for (int s = 0; s < STAGES - 1; s++) {
        uint32_t base = smem + s * STAGE_BYTES;
        #pragma unroll
        for (int p = 0; p < 4; p++) {
            cp16(base + ld_soff + p * 32 * 128,           gA + (size_t)s * BK + (size_t)p * 32 * IN_F);
            cp16(base + A_BYTES + ld_soff + p * 32 * 128, gB + (size_t)s * BK + (size_t)p * 32 * IN_F);
        }
        cp_commit();
    }
    gA += (STAGES - 1) * BK;
    gB += (STAGES - 1) * BK;

    uint32_t sc = smem;
    uint32_t sfill = smem + (STAGES - 1) * STAGE_BYTES;
    const uint32_t ring_end = smem + STAGES * STAGE_BYTES;

    uint32_t af[2][4][4], bf[2][2][4];   // double-buffered fragments

    // ---- mainloop ----
    for (int kt = 0; kt < K_ITERS; kt++) {
        cp_wait<STAGES - 2>();
        __syncthreads();
        const bool fill = (kt + STAGES - 1 < K_ITERS);

        // frag prefetch for ks = 0
        {
            const uint32_t swz0 = (uint32_t)((hi ^ lo) << 4);
            #pragma unroll
            for (int mi = 0; mi < 4; mi++) ldsm4(af[0][mi], sc + a_base[mi] + swz0);
            #pragma unroll
            for (int ni = 0; ni < 2; ni++) ldsm4(bf[0][ni], sc + b_base[ni] + swz0);
        }

        #pragma unroll
        for (int ks = 0; ks < BK / 16; ks++) {
            const int cur = ks & 1, nx = cur ^ 1;

            // fill first: fire-and-forget cp.async gets maximal lead time
            if (fill) {
                cp16(sfill + ld_soff + ks * 32 * 128,           gA + (size_t)ks * 32 * IN_F);
                cp16(sfill + A_BYTES + ld_soff + ks * 32 * 128, gB + (size_t)ks * 32 * IN_F);
            }

            // first half of MMAs (mi 0,1)
            #pragma unroll
            for (int mi = 0; mi < 2; mi++) {
                #pragma unroll
                for (int ni = 0; ni < 2; ni++) {
                    mma16816(acc[mi][2 * ni + 0], af[cur][mi], bf[cur][ni][0], bf[cur][ni][2]);
                    mma16816(acc[mi][2 * ni + 1], af[cur][mi], bf[cur][ni][1], bf[cur][ni][3]);
                }
            }

            // LDSM prefetch for next ks, sandwiched between MMA halves
            if (ks < BK / 16 - 1) {
                const uint32_t swz = (uint32_t)((((ks + 1) * 2 + hi) ^ lo) << 4);
                #pragma unroll
                for (int mi = 0; mi < 4; mi++) ldsm4(af[nx][mi], sc + a_base[mi] + swz);
                #pragma unroll
                for (int ni = 0; ni < 2; ni++) ldsm4(bf[nx][ni], sc + b_base[ni] + swz);
            }

            // second half of MMAs (mi 2,3) — covers LDSM latency
            #pragma unroll
            for (int mi = 2; mi < 4; mi++) {
                #pragma unroll
                for (int ni = 0; ni < 2; ni++) {
                    mma16816(acc[mi][2 * ni + 0], af[cur][mi], bf[cur][ni][0], bf[cur][ni][2]);
                    mma16816(acc[mi][2 * ni + 1], af[cur][mi], bf[cur][ni][1], bf[cur][ni][3]);
                }
            }
        }
        cp_commit();
        sc += STAGE_BYTES;    if (sc == ring_end) sc = smem;
        sfill += STAGE_BYTES; if (sfill == ring_end) sfill = smem;
        gA += BK;
        gB += BK;
    }

    // ---- epilogue: streaming stores (keep output out of L2) ----
    const int er = m0 + wm + (lane >> 2);
    const int ec = n0 + wn + ((lane & 3) << 1);
    #pragma unroll
    for (int mi = 0; mi < 4; mi++) {
        #pragma unroll
        for (int nj = 0; nj < 4; nj++) {
            const int row = er + mi * 16;
            const int col = ec + nj * 8;
            float2 bv = *reinterpret_cast<const float2*>(&bias[col]);
            float2 v0 = { acc[mi][nj][0] + bv.x, acc[mi][nj][1] + bv.y };
            float2 v1 = { acc[mi][nj][2] + bv.x, acc[mi][nj][3] + bv.y };
            __stcs(reinterpret_cast<float2*>(&out[(size_t)row * OUT_F + col]), v0);
            __stcs(reinterpret_cast<float2*>(&out[(size_t)(row + 8) * OUT_F + col]), v1);
        }
    }
}

// ---------------------------------------------------------------------------
// Host
// ---------------------------------------------------------------------------
extern "C" void kernel_launch(void* const* d_in, const int* in_sizes, int n_in,
                              void* d_out, int out_size)
{
    const float* x      = (const float*)d_in[0];
    const int*   w_idx  = (const int*)d_in[1];
    const float* absmax = (const float*)d_in[2];
    const float* bias   = (const float*)d_in[3];
    float*       out    = (float*)d_out;

    prep_kernel<<<WB + XB, 256>>>(x, w_idx, absmax);

    cudaFuncSetAttribute(gemm_kernel, cudaFuncAttributeMaxDynamicSharedMemorySize, SMEM_DYN);
    gemm_kernel<<<TILES_M * TILES_N, 256, SMEM_DYN>>>(bias, out);
    (void)in_sizes; (void)n_in; (void)out_size;
}